// round 14
// baseline (speedup 1.0000x reference)
#include <cuda_runtime.h>
#include <math_constants.h>

#define L 1024
#define CS 256
#define CZ 128
#define NH 8
#define DH 32
#define NSPLIT 4
#define BM 64
#define BN 64
#define LN_EPS 1e-5f
#define QK_SCALE 0.17677669529663687f  // 1/sqrt(32)

// f32x2 packed math (sm_103a)
#define PACKF2(d, lo, hi) \
    asm("mov.b64 %0, {%1, %2};" : "=l"(d) : "r"(__float_as_uint(lo)), "r"(__float_as_uint(hi)))
#define UNPACKF2(lo, hi, v) \
    do { unsigned _ulo, _uhi; \
         asm("mov.b64 {%0, %1}, %2;" : "=r"(_ulo), "=r"(_uhi) : "l"(v)); \
         lo = __uint_as_float(_ulo); hi = __uint_as_float(_uhi); } while (0)
#define FMA_F32X2(d, a, b, c) \
    asm("fma.rn.f32x2 %0, %1, %2, %3;" : "=l"(d) : "l"(a), "l"(b), "l"(c))
#define ADD_F32X2(d, a, b) \
    asm("add.rn.f32x2 %0, %1, %2;" : "=l"(d) : "l"(a), "l"(b))

// 16B-group swizzled slot for d-tiles: row r (0..63), 16B group d4 (0..7)
#define KSLOT(r, d4) ((r) * 32 + (((d4) ^ (((r) >> 2) & 7)) << 2))

// ---------------- scratch (device globals; no allocation allowed) ----------------
__device__ float d_sln[L * CS];
__device__ float d_Q[L * CS];
__device__ float d_K[L * CS];
__device__ float d_V[L * CS];
__device__ float d_G[L * CS];
__device__ float d_Bt[(size_t)L * NH * L];             // bias transposed: [i][h][j], 32 MB
__device__ float d_AO[L * CS];                         // G * attn_out
__device__ float d_pO[NSPLIT * NH * L * DH];           // split attention partial O
__device__ float2 d_pml[NSPLIT * NH * L];              // split attention partial (m, l)
__device__ float4 d_GW4g[256];                         // packed g*Wb, idx q*32+h*4+k, c=(q+8k)*4
__device__ float d_SgWg[NH], d_SbWg[NH];

// ---------------- Kernel 0: one-block prep of GW / SgW / SbW ----------------
__global__ __launch_bounds__(256) void zprep_kernel(const float* __restrict__ gz,
                                                    const float* __restrict__ bz,
                                                    const float* __restrict__ Wb) {
    int t = threadIdx.x;
    {
        int q = t >> 5, h = (t >> 2) & 7, k = t & 3;
        int c = (q + 8 * k) * 4;
        d_GW4g[q * 32 + h * 4 + k] =
            make_float4(gz[c] * Wb[c * NH + h], gz[c + 1] * Wb[(c + 1) * NH + h],
                        gz[c + 2] * Wb[(c + 2) * NH + h], gz[c + 3] * Wb[(c + 3) * NH + h]);
    }
    if (t < 16) {
        int h = t & 7;
        float acc = 0.f;
        if (t < 8) {
            for (int c = 0; c < CZ; c++) acc = fmaf(gz[c], Wb[c * NH + h], acc);
            d_SgWg[h] = acc;
        } else {
            for (int c = 0; c < CZ; c++) acc = fmaf(bz[c], Wb[c * NH + h], acc);
            d_SbWg[h] = acc;
        }
    }
}

// ---------------- Kernel 1: LayerNorm(s) ----------------
__global__ __launch_bounds__(256) void ln_s_kernel(const float* __restrict__ s,
                                                   const float* __restrict__ g,
                                                   const float* __restrict__ b) {
    int r = blockIdx.x, t = threadIdx.x;
    float v = s[r * CS + t];
    __shared__ float red[8];

    float sum = v;
#pragma unroll
    for (int off = 16; off > 0; off >>= 1) sum += __shfl_xor_sync(0xffffffffu, sum, off);
    if ((t & 31) == 0) red[t >> 5] = sum;
    __syncthreads();
    float tot = 0.f;
#pragma unroll
    for (int k = 0; k < 8; k++) tot += red[k];
    float mean = tot * (1.f / CS);
    float d = v - mean;
    __syncthreads();

    float sq = d * d;
#pragma unroll
    for (int off = 16; off > 0; off >>= 1) sq += __shfl_xor_sync(0xffffffffu, sq, off);
    if ((t & 31) == 0) red[t >> 5] = sq;
    __syncthreads();
    float tot2 = 0.f;
#pragma unroll
    for (int k = 0; k < 8; k++) tot2 += red[k];
    float rstd = rsqrtf(tot2 * (1.f / CS) + LN_EPS);

    d_sln[r * CS + t] = d * rstd * g[t] + b[t];
}

// ---------------- shared GEMM tile helper ----------------
__device__ __forceinline__ void gemm_tile_64x64(const float* __restrict__ A,
                                                const float* __restrict__ Bm,
                                                int m0, int n0, float acc[4][4]) {
    __shared__ float As[64][33];
    __shared__ float Bs[32][65];
    int t = threadIdx.x;
    int tx = t & 15, ty = t >> 4;

    for (int k0 = 0; k0 < 256; k0 += 32) {
        int ra = t >> 2, ca = (t & 3) * 8;
#pragma unroll
        for (int q = 0; q < 8; q++) As[ra][ca + q] = A[(m0 + ra) * 256 + k0 + ca + q];
        int rb = t >> 3, cb = (t & 7) * 8;
#pragma unroll
        for (int q = 0; q < 8; q++) Bs[rb][cb + q] = Bm[(k0 + rb) * 256 + n0 + cb + q];
        __syncthreads();
#pragma unroll 8
        for (int kk = 0; kk < 32; kk++) {
            float a[4], bb[4];
#pragma unroll
            for (int ii = 0; ii < 4; ii++) a[ii] = As[ty * 4 + ii][kk];
#pragma unroll
            for (int jj = 0; jj < 4; jj++) bb[jj] = Bs[kk][tx * 4 + jj];
#pragma unroll
            for (int ii = 0; ii < 4; ii++)
#pragma unroll
                for (int jj = 0; jj < 4; jj++) acc[ii][jj] = fmaf(a[ii], bb[jj], acc[ii][jj]);
        }
        __syncthreads();
    }
}

// ---------------- Kernel 2: QKVG projections ----------------
__global__ __launch_bounds__(256) void gemm_qkvg_kernel(const float* __restrict__ Wq,
                                                        const float* __restrict__ bq,
                                                        const float* __restrict__ Wk,
                                                        const float* __restrict__ Wv,
                                                        const float* __restrict__ Wg) {
    const float* Bm;
    float* C;
    int mode;
    switch (blockIdx.z) {
        case 0: Bm = Wq; C = d_Q; mode = 1; break;
        case 1: Bm = Wk; C = d_K; mode = 0; break;
        case 2: Bm = Wv; C = d_V; mode = 0; break;
        default: Bm = Wg; C = d_G; mode = 2; break;
    }
    int m0 = blockIdx.x * 64, n0 = blockIdx.y * 64;
    float acc[4][4] = {};
    gemm_tile_64x64(d_sln, Bm, m0, n0, acc);

    int tx = threadIdx.x & 15, ty = threadIdx.x >> 4;
#pragma unroll
    for (int ii = 0; ii < 4; ii++)
#pragma unroll
        for (int jj = 0; jj < 4; jj++) {
            int mI = m0 + ty * 4 + ii, nI = n0 + tx * 4 + jj;
            float v = acc[ii][jj];
            if (mode == 1) v += bq[nI];
            if (mode == 2) v = 1.f / (1.f + __expf(-v));
            C[mI * 256 + nI] = v;
        }
}

// ---------------- Kernel 3: zln_bias v10 — v9 + occupancy 4 blocks/SM, pipelined k-loop ----------------
__global__ __launch_bounds__(256, 4) void zln_bias_kernel(const float* __restrict__ z) {
    __shared__ ulonglong2 GW2[8][33];
    __shared__ float sB[NH * 68];

    int t = threadIdx.x;
    int i = blockIdx.y;
    int jbase = blockIdx.x * 64;
    int rr = t >> 3, q = t & 7;

    {
        float4 w = d_GW4g[t];
        ulonglong2 p;
        PACKF2(p.x, w.x, w.y);
        PACKF2(p.y, w.z, w.w);
        GW2[t >> 5][t & 31] = p;
    }
    float Sg = d_SgWg[q], Sb = d_SbWg[q];
    __syncthreads();

    const float* rowA = z + ((size_t)i * L + jbase + rr) * CZ;
    const float* rowB = rowA + (size_t)32 * CZ;

    unsigned long long paA[8] = {}, paB[8] = {};
    unsigned long long s1A = 0ull, s2A = 0ull, s1B = 0ull, s2B = 0ull;
#pragma unroll 2
    for (int k = 0; k < 4; k++) {
        int off = (q + 8 * k) * 4;
        const float4 va = *(const float4*)(rowA + off);
        const float4 vb = *(const float4*)(rowB + off);
        unsigned long long a01, a23, b01, b23;
        PACKF2(a01, va.x, va.y);
        PACKF2(a23, va.z, va.w);
        PACKF2(b01, vb.x, vb.y);
        PACKF2(b23, vb.z, vb.w);
#pragma unroll
        for (int h = 0; h < 8; h++) {
            ulonglong2 w = GW2[q][h * 4 + k];
            FMA_F32X2(paA[h], a01, w.x, paA[h]);
            FMA_F32X2(paA[h], a23, w.y, paA[h]);
            FMA_F32X2(paB[h], b01, w.x, paB[h]);
            FMA_F32X2(paB[h], b23, w.y, paB[h]);
        }
        FMA_F32X2(s2A, a01, a01, s2A);
        FMA_F32X2(s2A, a23, a23, s2A);
        ADD_F32X2(s1A, s1A, a01);
        ADD_F32X2(s1A, s1A, a23);
        FMA_F32X2(s2B, b01, b01, s2B);
        FMA_F32X2(s2B, b23, b23, s2B);
        ADD_F32X2(s1B, s1B, b01);
        ADD_F32X2(s1B, s1B, b23);
    }

    float vA[8], vB[8];
#pragma unroll
    for (int h = 0; h < 8; h++) {
        float lo, hi;
        UNPACKF2(lo, hi, paA[h]);
        vA[h] = lo + hi;
        UNPACKF2(lo, hi, paB[h]);
        vB[h] = lo + hi;
    }
    float s1Af, s2Af, s1Bf, s2Bf;
    {
        float l1, h1;
        UNPACKF2(l1, h1, s1A); s1Af = l1 + h1;
        UNPACKF2(l1, h1, s2A); s2Af = l1 + h1;
        UNPACKF2(l1, h1, s1B); s1Bf = l1 + h1;
        UNPACKF2(l1, h1, s2B); s2Bf = l1 + h1;
    }

    // folded butterfly over the 8 q-lanes; lane q ends with head q
    bool h4 = (t & 4) != 0;
    float wA[4], wB[4];
#pragma unroll
    for (int k = 0; k < 4; k++) {
        float sA = h4 ? vA[k] : vA[k + 4];
        float sBv = h4 ? vB[k] : vB[k + 4];
        float rA = __shfl_xor_sync(0xffffffffu, sA, 4);
        float rB = __shfl_xor_sync(0xffffffffu, sBv, 4);
        wA[k] = (h4 ? vA[k + 4] : vA[k]) + rA;
        wB[k] = (h4 ? vB[k + 4] : vB[k]) + rB;
    }
    bool h2 = (t & 2) != 0;
    float xA[2], xB[2];
#pragma unroll
    for (int k = 0; k < 2; k++) {
        float sA = h2 ? wA[k] : wA[k + 2];
        float sBv = h2 ? wB[k] : wB[k + 2];
        float rA = __shfl_xor_sync(0xffffffffu, sA, 2);
        float rB = __shfl_xor_sync(0xffffffffu, sBv, 2);
        xA[k] = (h2 ? wA[k + 2] : wA[k]) + rA;
        xB[k] = (h2 ? wB[k + 2] : wB[k]) + rB;
    }
    bool h1 = (t & 1) != 0;
    float aA, aB;
    {
        float sA = h1 ? xA[0] : xA[1];
        float sBv = h1 ? xB[0] : xB[1];
        float rA = __shfl_xor_sync(0xffffffffu, sA, 1);
        float rB = __shfl_xor_sync(0xffffffffu, sBv, 1);
        aA = (h1 ? xA[1] : xA[0]) + rA;
        aB = (h1 ? xB[1] : xB[0]) + rB;
    }
#pragma unroll
    for (int m = 4; m > 0; m >>= 1) {
        s1Af += __shfl_xor_sync(0xffffffffu, s1Af, m);
        s2Af += __shfl_xor_sync(0xffffffffu, s2Af, m);
        s1Bf += __shfl_xor_sync(0xffffffffu, s1Bf, m);
        s2Bf += __shfl_xor_sync(0xffffffffu, s2Bf, m);
    }

    {
        float meanA = s1Af * (1.f / CZ);
        float rstdA = rsqrtf(s2Af * (1.f / CZ) - meanA * meanA + LN_EPS);
        float mrA = meanA * rstdA;
        sB[q * 68 + rr] = rstdA * aA - mrA * Sg + Sb;

        float meanB = s1Bf * (1.f / CZ);
        float rstdB = rsqrtf(s2Bf * (1.f / CZ) - meanB * meanB + LN_EPS);
        float mrB = meanB * rstdB;
        sB[q * 68 + rr + 32] = rstdB * aB - mrB * Sg + Sb;
    }
    __syncthreads();

    {
        int h = t >> 5, col = t & 31;
        size_t base = ((size_t)i * NH + h) * L + jbase;
        d_Bt[base + col] = sB[h * 68 + col];
        d_Bt[base + col + 32] = sB[h * 68 + col + 32];
    }
}

// ---------------- Kernel 4a: split attention, swizzled Q/K tiles + LDS.128 S-compute ----------------
__global__ __launch_bounds__(256, 3) void attn_split_kernel(const int* __restrict__ mask) {
    __shared__ float Qs[BM * 32];        // swizzled, KSLOT layout
    __shared__ float Ks[BN * 32];        // swizzled
    __shared__ float Vs[BN][32];
    __shared__ float Ss[BM][67];
    __shared__ float row_m[BM], row_l[BM], row_alpha[BM];
    __shared__ unsigned char ms[BN];

    int t = threadIdx.x;
    int h = blockIdx.y;
    int i0 = blockIdx.x * BM;
    int split = blockIdx.z;
    int tx = t & 15, ty = t >> 4;

#pragma unroll
    for (int rep = 0; rep < 2; rep++) {
        int idx = t + rep * 256;
        int r = idx >> 3, c4 = idx & 7;
        float4 q4 = *(const float4*)&d_Q[(i0 + r) * CS + h * DH + c4 * 4];
        q4.x *= QK_SCALE; q4.y *= QK_SCALE; q4.z *= QK_SCALE; q4.w *= QK_SCALE;
        *(float4*)&Qs[KSLOT(r, c4)] = q4;
    }
    if (t < BM) { row_m[t] = -CUDART_INF_F; row_l[t] = 0.f; }

    int dg = t & 7;
    int r0 = (t >> 3) * 2;
    float4 O0 = make_float4(0.f, 0.f, 0.f, 0.f);
    float4 O1 = make_float4(0.f, 0.f, 0.f, 0.f);

    for (int jt = 0; jt < 4; jt++) {
        int j0 = split * 256 + jt * BN;
        __syncthreads();
#pragma unroll
        for (int rep = 0; rep < 2; rep++) {
            int idx = t + rep * 256;
            int r = idx >> 3, c4 = idx & 7;
            float4 k4 = *(const float4*)&d_K[(j0 + r) * CS + h * DH + c4 * 4];
            *(float4*)&Ks[KSLOT(r, c4)] = k4;
            *(float4*)&Vs[r][c4 * 4] = *(const float4*)&d_V[(j0 + r) * CS + h * DH + c4 * 4];
        }
        if (t < BN) ms[t] = (unsigned char)(mask[j0 + t] != 0);
        __syncthreads();

        float sacc[4][4] = {};
#pragma unroll
        for (int d4 = 0; d4 < 8; d4++) {
            float4 a4[4];
#pragma unroll
            for (int ii = 0; ii < 4; ii++) a4[ii] = *(const float4*)&Qs[KSLOT(ty * 4 + ii, d4)];
#pragma unroll
            for (int jj = 0; jj < 4; jj++) {
                float4 b4 = *(const float4*)&Ks[KSLOT(tx * 4 + jj, d4)];
#pragma unroll
                for (int ii = 0; ii < 4; ii++) {
                    sacc[ii][jj] = fmaf(a4[ii].x, b4.x, sacc[ii][jj]);
                    sacc[ii][jj] = fmaf(a4[ii].y, b4.y, sacc[ii][jj]);
                    sacc[ii][jj] = fmaf(a4[ii].z, b4.z, sacc[ii][jj]);
                    sacc[ii][jj] = fmaf(a4[ii].w, b4.w, sacc[ii][jj]);
                }
            }
        }
#pragma unroll
        for (int ii = 0; ii < 4; ii++) {
            int iI = ty * 4 + ii;
            const float4 bv = *(const float4*)&d_Bt[(size_t)(i0 + iI) * (NH * L) + h * L + j0 + tx * 4];
            float bb4[4] = {bv.x, bv.y, bv.z, bv.w};
#pragma unroll
            for (int jj = 0; jj < 4; jj++) {
                int jl = tx * 4 + jj;
                Ss[iI][jl] = ms[jl] ? (sacc[ii][jj] + bb4[jj]) : -CUDART_INF_F;
            }
        }
        __syncthreads();

        {
            int rw = t >> 2, gq = t & 3;
            float mold = row_m[rw];
            float mx = -CUDART_INF_F;
#pragma unroll
            for (int qq = 0; qq < 16; qq++) mx = fmaxf(mx, Ss[rw][gq * 16 + qq]);
            mx = fmaxf(mx, __shfl_xor_sync(0xffffffffu, mx, 1));
            mx = fmaxf(mx, __shfl_xor_sync(0xffffffffu, mx, 2));
            float nm = fmaxf(mold, mx);
            float alpha = (nm == -CUDART_INF_F) ? 1.f : __expf(mold - nm);
            float ps = 0.f;
#pragma unroll
            for (int qq = 0; qq < 16; qq++) {
                float sv = Ss[rw][gq * 16 + qq];
                float p = (sv == -CUDART_INF_F) ? 0.f : __expf(sv - nm);
                Ss[rw][gq * 16 + qq] = p;
                ps += p;
            }
            ps += __shfl_xor_sync(0xffffffffu, ps, 1);
            ps += __shfl_xor_sync(0xffffffffu, ps, 2);
            if (gq == 0) {
                row_m[rw] = nm;
                row_l[rw] = row_l[rw] * alpha + ps;
                row_alpha[rw] = alpha;
            }
        }
        __syncthreads();

        {
            float a0 = row_alpha[r0], a1 = row_alpha[r0 + 1];
            O0.x *= a0; O0.y *= a0; O0.z *= a0; O0.w *= a0;
            O1.x *= a1; O1.y *= a1; O1.z *= a1; O1.w *= a1;
#pragma unroll 4
            for (int j = 0; j < BN; j++) {
                float p0 = Ss[r0][j];
                float p1 = Ss[r0 + 1][j];
                const float4 v = *(const float4*)&Vs[j][dg * 4];
                O0.x = fmaf(p0, v.x, O0.x);
                O0.y = fmaf(p0, v.y, O0.y);
                O0.z = fmaf(p0, v.z, O0.z);
                O0.w = fmaf(p0, v.w, O0.w);
                O1.x = fmaf(p1, v.x, O1.x);
                O1.y = fmaf(p1, v.y, O1.y);
                O1.z = fmaf(p1, v.z, O1.z);
                O1.w = fmaf(p1, v.w, O1.w);
            }
        }
    }

    {
        size_t b0 = (((size_t)(split * NH + h)) * L + i0 + r0) * DH + dg * 4;
        *(float4*)&d_pO[b0] = O0;
        *(float4*)&d_pO[b0 + DH] = O1;
        if (t < BM) d_pml[((split * NH + h) * L) + i0 + t] = make_float2(row_m[t], row_l[t]);
    }
}

// ---------------- Kernel 4b: combine splits, apply 1/l and G gate ----------------
__global__ __launch_bounds__(256) void attn_combine_kernel() {
    int t = threadIdx.x;
    int i = blockIdx.x;
    int h = t >> 5, lane = t & 31;

    float2 ml[NSPLIT];
    float mx = -CUDART_INF_F;
#pragma unroll
    for (int s = 0; s < NSPLIT; s++) {
        ml[s] = d_pml[((s * NH + h) * L) + i];
        mx = fmaxf(mx, ml[s].x);
    }
    float lsum = 0.f, o = 0.f;
#pragma unroll
    for (int s = 0; s < NSPLIT; s++) {
        float w = (ml[s].x == -CUDART_INF_F) ? 0.f : __expf(ml[s].x - mx);
        lsum = fmaf(ml[s].y, w, lsum);
        o = fmaf(d_pO[(((s * NH + h) * L) + i) * DH + lane], w, o);
    }
    float rl = (lsum > 0.f) ? (1.f / lsum) : 0.f;
    int base = i * CS + h * DH + lane;
    d_AO[base] = o * rl * d_G[base];
}

// ---------------- Kernel 5: ds = (G*out) @ Wo * mask ----------------
__global__ __launch_bounds__(256) void gemm_out_kernel(const float* __restrict__ Wo,
                                                       const int* __restrict__ mask,
                                                       float* __restrict__ out) {
    int m0 = blockIdx.x * 64, n0 = blockIdx.y * 64;
    float acc[4][4] = {};
    gemm_tile_64x64(d_AO, Wo, m0, n0, acc);

    int tx = threadIdx.x & 15, ty = threadIdx.x >> 4;
#pragma unroll
    for (int ii = 0; ii < 4; ii++) {
        int mI = m0 + ty * 4 + ii;
        float mk = (mask[mI] != 0) ? 1.f : 0.f;
#pragma unroll
        for (int jj = 0; jj < 4; jj++) {
            int nI = n0 + tx * 4 + jj;
            out[mI * 256 + nI] = acc[ii][jj] * mk;
        }
    }
}

// ---------------- side stream (static init; deltas settle before checkpoints) ----------------
__global__ void warmup_kernel() {}

namespace {
struct SideStream {
    cudaStream_t s;
    cudaEvent_t fork, join;
    SideStream() {
        cudaStreamCreateWithFlags(&s, cudaStreamNonBlocking);
        cudaEventCreateWithFlags(&fork, cudaEventDisableTiming);
        cudaEventCreateWithFlags(&join, cudaEventDisableTiming);
        warmup_kernel<<<1, 32, 0, s>>>();
        warmup_kernel<<<1, 32>>>();
        cudaDeviceSynchronize();
    }
};
SideStream g_ss;
}

// ---------------- launch (R11 schedule: zln forked whole, joined before attention) ----------------
extern "C" void kernel_launch(void* const* d_in, const int* in_sizes, int n_in,
                              void* d_out, int out_size) {
    const float* s = (const float*)d_in[0];
    const float* z = (const float*)d_in[1];
    const int* res_mask = (const int*)d_in[2];
    const float* g_s = (const float*)d_in[3];
    const float* b_s = (const float*)d_in[4];
    const float* g_z = (const float*)d_in[5];
    const float* b_z = (const float*)d_in[6];
    const float* Wq = (const float*)d_in[7];
    const float* bq = (const float*)d_in[8];
    const float* Wk = (const float*)d_in[9];
    const float* Wv = (const float*)d_in[10];
    const float* Wb = (const float*)d_in[11];
    const float* Wg = (const float*)d_in[12];
    const float* Wo = (const float*)d_in[13];
    float* out = (float*)d_out;

    cudaEventRecord(g_ss.fork, 0);
    cudaStreamWaitEvent(g_ss.s, g_ss.fork, 0);

    zprep_kernel<<<1, 256, 0, g_ss.s>>>(g_z, b_z, Wb);
    zln_bias_kernel<<<dim3(16, L), 256, 0, g_ss.s>>>(z);

    ln_s_kernel<<<L, 256>>>(s, g_s, b_s);
    gemm_qkvg_kernel<<<dim3(16, 4, 4), 256>>>(Wq, bq, Wk, Wv, Wg);

    cudaEventRecord(g_ss.join, g_ss.s);
    cudaStreamWaitEvent(0, g_ss.join, 0);

    attn_split_kernel<<<dim3(16, 8, NSPLIT), 256>>>(res_mask);
    attn_combine_kernel<<<L, 256>>>();
    gemm_out_kernel<<<dim3(16, 4), 256>>>(Wo, res_mask, out);
}

// round 15
// speedup vs baseline: 1.0760x; 1.0760x over previous
#include <cuda_runtime.h>
#include <math_constants.h>

#define L 1024
#define CS 256
#define CZ 128
#define NH 8
#define DH 32
#define NSPLIT 4
#define BM 64
#define BN 64
#define LN_EPS 1e-5f
#define QK_SCALE 0.17677669529663687f  // 1/sqrt(32)

// f32x2 packed math (sm_103a)
#define PACKF2(d, lo, hi) \
    asm("mov.b64 %0, {%1, %2};" : "=l"(d) : "r"(__float_as_uint(lo)), "r"(__float_as_uint(hi)))
#define UNPACKF2(lo, hi, v) \
    do { unsigned _ulo, _uhi; \
         asm("mov.b64 {%0, %1}, %2;" : "=r"(_ulo), "=r"(_uhi) : "l"(v)); \
         lo = __uint_as_float(_ulo); hi = __uint_as_float(_uhi); } while (0)
#define FMA_F32X2(d, a, b, c) \
    asm("fma.rn.f32x2 %0, %1, %2, %3;" : "=l"(d) : "l"(a), "l"(b), "l"(c))
#define ADD_F32X2(d, a, b) \
    asm("add.rn.f32x2 %0, %1, %2;" : "=l"(d) : "l"(a), "l"(b))

// 16B-group swizzled slot for d-tiles: row r (0..63), 16B group d4 (0..7)
#define KSLOT(r, d4) ((r) * 32 + (((d4) ^ (((r) >> 2) & 7)) << 2))

// ---------------- scratch (device globals; no allocation allowed) ----------------
__device__ float d_sln[L * CS];
__device__ float d_Q[L * CS];
__device__ float d_K[L * CS];
__device__ float d_V[L * CS];
__device__ float d_G[L * CS];
__device__ float d_Bt[(size_t)L * NH * L];             // bias transposed: [i][h][j], 32 MB
__device__ float d_pO[NSPLIT * NH * L * DH];           // split attention partial O
__device__ float2 d_pml[NSPLIT * NH * L];              // split attention partial (m, l)
__device__ float4 d_GW4g[256];                         // packed g*Wb, idx q*32+h*4+k, c=(q+8k)*4
__device__ float d_SgWg[NH], d_SbWg[NH];

// ---------------- Kernel 0: one-block prep of GW / SgW / SbW ----------------
__global__ __launch_bounds__(256) void zprep_kernel(const float* __restrict__ gz,
                                                    const float* __restrict__ bz,
                                                    const float* __restrict__ Wb) {
    int t = threadIdx.x;
    {
        int q = t >> 5, h = (t >> 2) & 7, k = t & 3;
        int c = (q + 8 * k) * 4;
        d_GW4g[q * 32 + h * 4 + k] =
            make_float4(gz[c] * Wb[c * NH + h], gz[c + 1] * Wb[(c + 1) * NH + h],
                        gz[c + 2] * Wb[(c + 2) * NH + h], gz[c + 3] * Wb[(c + 3) * NH + h]);
    }
    if (t < 16) {
        int h = t & 7;
        float acc = 0.f;
        if (t < 8) {
            for (int c = 0; c < CZ; c++) acc = fmaf(gz[c], Wb[c * NH + h], acc);
            d_SgWg[h] = acc;
        } else {
            for (int c = 0; c < CZ; c++) acc = fmaf(bz[c], Wb[c * NH + h], acc);
            d_SbWg[h] = acc;
        }
    }
}

// ---------------- Kernel 1: LayerNorm(s) ----------------
__global__ __launch_bounds__(256) void ln_s_kernel(const float* __restrict__ s,
                                                   const float* __restrict__ g,
                                                   const float* __restrict__ b) {
    int r = blockIdx.x, t = threadIdx.x;
    float v = s[r * CS + t];
    __shared__ float red[8];

    float sum = v;
#pragma unroll
    for (int off = 16; off > 0; off >>= 1) sum += __shfl_xor_sync(0xffffffffu, sum, off);
    if ((t & 31) == 0) red[t >> 5] = sum;
    __syncthreads();
    float tot = 0.f;
#pragma unroll
    for (int k = 0; k < 8; k++) tot += red[k];
    float mean = tot * (1.f / CS);
    float d = v - mean;
    __syncthreads();

    float sq = d * d;
#pragma unroll
    for (int off = 16; off > 0; off >>= 1) sq += __shfl_xor_sync(0xffffffffu, sq, off);
    if ((t & 31) == 0) red[t >> 5] = sq;
    __syncthreads();
    float tot2 = 0.f;
#pragma unroll
    for (int k = 0; k < 8; k++) tot2 += red[k];
    float rstd = rsqrtf(tot2 * (1.f / CS) + LN_EPS);

    d_sln[r * CS + t] = d * rstd * g[t] + b[t];
}

// ---------------- shared GEMM tile helper (used by qkvg) ----------------
__device__ __forceinline__ void gemm_tile_64x64(const float* __restrict__ A,
                                                const float* __restrict__ Bm,
                                                int m0, int n0, float acc[4][4]) {
    __shared__ float As[64][33];
    __shared__ float Bs[32][65];
    int t = threadIdx.x;
    int tx = t & 15, ty = t >> 4;

    for (int k0 = 0; k0 < 256; k0 += 32) {
        int ra = t >> 2, ca = (t & 3) * 8;
#pragma unroll
        for (int q = 0; q < 8; q++) As[ra][ca + q] = A[(m0 + ra) * 256 + k0 + ca + q];
        int rb = t >> 3, cb = (t & 7) * 8;
#pragma unroll
        for (int q = 0; q < 8; q++) Bs[rb][cb + q] = Bm[(k0 + rb) * 256 + n0 + cb + q];
        __syncthreads();
#pragma unroll 8
        for (int kk = 0; kk < 32; kk++) {
            float a[4], bb[4];
#pragma unroll
            for (int ii = 0; ii < 4; ii++) a[ii] = As[ty * 4 + ii][kk];
#pragma unroll
            for (int jj = 0; jj < 4; jj++) bb[jj] = Bs[kk][tx * 4 + jj];
#pragma unroll
            for (int ii = 0; ii < 4; ii++)
#pragma unroll
                for (int jj = 0; jj < 4; jj++) acc[ii][jj] = fmaf(a[ii], bb[jj], acc[ii][jj]);
        }
        __syncthreads();
    }
}

// ---------------- Kernel 2: QKVG projections ----------------
__global__ __launch_bounds__(256) void gemm_qkvg_kernel(const float* __restrict__ Wq,
                                                        const float* __restrict__ bq,
                                                        const float* __restrict__ Wk,
                                                        const float* __restrict__ Wv,
                                                        const float* __restrict__ Wg) {
    const float* Bm;
    float* C;
    int mode;
    switch (blockIdx.z) {
        case 0: Bm = Wq; C = d_Q; mode = 1; break;
        case 1: Bm = Wk; C = d_K; mode = 0; break;
        case 2: Bm = Wv; C = d_V; mode = 0; break;
        default: Bm = Wg; C = d_G; mode = 2; break;
    }
    int m0 = blockIdx.x * 64, n0 = blockIdx.y * 64;
    float acc[4][4] = {};
    gemm_tile_64x64(d_sln, Bm, m0, n0, acc);

    int tx = threadIdx.x & 15, ty = threadIdx.x >> 4;
#pragma unroll
    for (int ii = 0; ii < 4; ii++)
#pragma unroll
        for (int jj = 0; jj < 4; jj++) {
            int mI = m0 + ty * 4 + ii, nI = n0 + tx * 4 + jj;
            float v = acc[ii][jj];
            if (mode == 1) v += bq[nI];
            if (mode == 2) v = 1.f / (1.f + __expf(-v));
            C[mI * 256 + nI] = v;
        }
}

// ---------------- Kernel 3: zln_bias v9 (R13 exact — proven 123.8us) ----------------
__global__ __launch_bounds__(256, 3) void zln_bias_kernel(const float* __restrict__ z) {
    __shared__ ulonglong2 GW2[8][33];
    __shared__ float sB[NH * 68];

    int t = threadIdx.x;
    int i = blockIdx.y;
    int jbase = blockIdx.x * 64;
    int rr = t >> 3, q = t & 7;

    {
        float4 w = d_GW4g[t];
        ulonglong2 p;
        PACKF2(p.x, w.x, w.y);
        PACKF2(p.y, w.z, w.w);
        GW2[t >> 5][t & 31] = p;
    }
    float Sg = d_SgWg[q], Sb = d_SbWg[q];
    __syncthreads();

    const float* rowA = z + ((size_t)i * L + jbase + rr) * CZ;
    const float* rowB = rowA + (size_t)32 * CZ;

    unsigned long long paA[8] = {}, paB[8] = {};
    unsigned long long s1A = 0ull, s2A = 0ull, s1B = 0ull, s2B = 0ull;
#pragma unroll
    for (int k = 0; k < 4; k++) {
        int off = (q + 8 * k) * 4;
        const float4 va = *(const float4*)(rowA + off);
        const float4 vb = *(const float4*)(rowB + off);
        unsigned long long a01, a23, b01, b23;
        PACKF2(a01, va.x, va.y);
        PACKF2(a23, va.z, va.w);
        PACKF2(b01, vb.x, vb.y);
        PACKF2(b23, vb.z, vb.w);
#pragma unroll
        for (int h = 0; h < 8; h++) {
            ulonglong2 w = GW2[q][h * 4 + k];
            FMA_F32X2(paA[h], a01, w.x, paA[h]);
            FMA_F32X2(paA[h], a23, w.y, paA[h]);
            FMA_F32X2(paB[h], b01, w.x, paB[h]);
            FMA_F32X2(paB[h], b23, w.y, paB[h]);
        }
        FMA_F32X2(s2A, a01, a01, s2A);
        FMA_F32X2(s2A, a23, a23, s2A);
        ADD_F32X2(s1A, s1A, a01);
        ADD_F32X2(s1A, s1A, a23);
        FMA_F32X2(s2B, b01, b01, s2B);
        FMA_F32X2(s2B, b23, b23, s2B);
        ADD_F32X2(s1B, s1B, b01);
        ADD_F32X2(s1B, s1B, b23);
    }

    float vA[8], vB[8];
#pragma unroll
    for (int h = 0; h < 8; h++) {
        float lo, hi;
        UNPACKF2(lo, hi, paA[h]);
        vA[h] = lo + hi;
        UNPACKF2(lo, hi, paB[h]);
        vB[h] = lo + hi;
    }
    float s1Af, s2Af, s1Bf, s2Bf;
    {
        float l1, h1;
        UNPACKF2(l1, h1, s1A); s1Af = l1 + h1;
        UNPACKF2(l1, h1, s2A); s2Af = l1 + h1;
        UNPACKF2(l1, h1, s1B); s1Bf = l1 + h1;
        UNPACKF2(l1, h1, s2B); s2Bf = l1 + h1;
    }

    bool h4 = (t & 4) != 0;
    float wA[4], wB[4];
#pragma unroll
    for (int k = 0; k < 4; k++) {
        float sA = h4 ? vA[k] : vA[k + 4];
        float sBv = h4 ? vB[k] : vB[k + 4];
        float rA = __shfl_xor_sync(0xffffffffu, sA, 4);
        float rB = __shfl_xor_sync(0xffffffffu, sBv, 4);
        wA[k] = (h4 ? vA[k + 4] : vA[k]) + rA;
        wB[k] = (h4 ? vB[k + 4] : vB[k]) + rB;
    }
    bool h2 = (t & 2) != 0;
    float xA[2], xB[2];
#pragma unroll
    for (int k = 0; k < 2; k++) {
        float sA = h2 ? wA[k] : wA[k + 2];
        float sBv = h2 ? wB[k] : wB[k + 2];
        float rA = __shfl_xor_sync(0xffffffffu, sA, 2);
        float rB = __shfl_xor_sync(0xffffffffu, sBv, 2);
        xA[k] = (h2 ? wA[k + 2] : wA[k]) + rA;
        xB[k] = (h2 ? wB[k + 2] : wB[k]) + rB;
    }
    bool h1 = (t & 1) != 0;
    float aA, aB;
    {
        float sA = h1 ? xA[0] : xA[1];
        float sBv = h1 ? xB[0] : xB[1];
        float rA = __shfl_xor_sync(0xffffffffu, sA, 1);
        float rB = __shfl_xor_sync(0xffffffffu, sBv, 1);
        aA = (h1 ? xA[1] : xA[0]) + rA;
        aB = (h1 ? xB[1] : xB[0]) + rB;
    }
#pragma unroll
    for (int m = 4; m > 0; m >>= 1) {
        s1Af += __shfl_xor_sync(0xffffffffu, s1Af, m);
        s2Af += __shfl_xor_sync(0xffffffffu, s2Af, m);
        s1Bf += __shfl_xor_sync(0xffffffffu, s1Bf, m);
        s2Bf += __shfl_xor_sync(0xffffffffu, s2Bf, m);
    }

    {
        float meanA = s1Af * (1.f / CZ);
        float rstdA = rsqrtf(s2Af * (1.f / CZ) - meanA * meanA + LN_EPS);
        float mrA = meanA * rstdA;
        sB[q * 68 + rr] = rstdA * aA - mrA * Sg + Sb;

        float meanB = s1Bf * (1.f / CZ);
        float rstdB = rsqrtf(s2Bf * (1.f / CZ) - meanB * meanB + LN_EPS);
        float mrB = meanB * rstdB;
        sB[q * 68 + rr + 32] = rstdB * aB - mrB * Sg + Sb;
    }
    __syncthreads();

    {
        int h = t >> 5, col = t & 31;
        size_t base = ((size_t)i * NH + h) * L + jbase;
        d_Bt[base + col] = sB[h * 68 + col];
        d_Bt[base + col + 32] = sB[h * 68 + col + 32];
    }
}

// ---------------- Kernel 4: split attention, swizzled Q/K tiles + LDS.128 S-compute ----------------
__global__ __launch_bounds__(256, 3) void attn_split_kernel(const int* __restrict__ mask) {
    __shared__ float Qs[BM * 32];
    __shared__ float Ks[BN * 32];
    __shared__ float Vs[BN][32];
    __shared__ float Ss[BM][67];
    __shared__ float row_m[BM], row_l[BM], row_alpha[BM];
    __shared__ unsigned char ms[BN];

    int t = threadIdx.x;
    int h = blockIdx.y;
    int i0 = blockIdx.x * BM;
    int split = blockIdx.z;
    int tx = t & 15, ty = t >> 4;

#pragma unroll
    for (int rep = 0; rep < 2; rep++) {
        int idx = t + rep * 256;
        int r = idx >> 3, c4 = idx & 7;
        float4 q4 = *(const float4*)&d_Q[(i0 + r) * CS + h * DH + c4 * 4];
        q4.x *= QK_SCALE; q4.y *= QK_SCALE; q4.z *= QK_SCALE; q4.w *= QK_SCALE;
        *(float4*)&Qs[KSLOT(r, c4)] = q4;
    }
    if (t < BM) { row_m[t] = -CUDART_INF_F; row_l[t] = 0.f; }

    int dg = t & 7;
    int r0 = (t >> 3) * 2;
    float4 O0 = make_float4(0.f, 0.f, 0.f, 0.f);
    float4 O1 = make_float4(0.f, 0.f, 0.f, 0.f);

    for (int jt = 0; jt < 4; jt++) {
        int j0 = split * 256 + jt * BN;
        __syncthreads();
#pragma unroll
        for (int rep = 0; rep < 2; rep++) {
            int idx = t + rep * 256;
            int r = idx >> 3, c4 = idx & 7;
            float4 k4 = *(const float4*)&d_K[(j0 + r) * CS + h * DH + c4 * 4];
            *(float4*)&Ks[KSLOT(r, c4)] = k4;
            *(float4*)&Vs[r][c4 * 4] = *(const float4*)&d_V[(j0 + r) * CS + h * DH + c4 * 4];
        }
        if (t < BN) ms[t] = (unsigned char)(mask[j0 + t] != 0);
        __syncthreads();

        float sacc[4][4] = {};
#pragma unroll
        for (int d4 = 0; d4 < 8; d4++) {
            float4 a4[4];
#pragma unroll
            for (int ii = 0; ii < 4; ii++) a4[ii] = *(const float4*)&Qs[KSLOT(ty * 4 + ii, d4)];
#pragma unroll
            for (int jj = 0; jj < 4; jj++) {
                float4 b4 = *(const float4*)&Ks[KSLOT(tx * 4 + jj, d4)];
#pragma unroll
                for (int ii = 0; ii < 4; ii++) {
                    sacc[ii][jj] = fmaf(a4[ii].x, b4.x, sacc[ii][jj]);
                    sacc[ii][jj] = fmaf(a4[ii].y, b4.y, sacc[ii][jj]);
                    sacc[ii][jj] = fmaf(a4[ii].z, b4.z, sacc[ii][jj]);
                    sacc[ii][jj] = fmaf(a4[ii].w, b4.w, sacc[ii][jj]);
                }
            }
        }
#pragma unroll
        for (int ii = 0; ii < 4; ii++) {
            int iI = ty * 4 + ii;
            const float4 bv = *(const float4*)&d_Bt[(size_t)(i0 + iI) * (NH * L) + h * L + j0 + tx * 4];
            float bb4[4] = {bv.x, bv.y, bv.z, bv.w};
#pragma unroll
            for (int jj = 0; jj < 4; jj++) {
                int jl = tx * 4 + jj;
                Ss[iI][jl] = ms[jl] ? (sacc[ii][jj] + bb4[jj]) : -CUDART_INF_F;
            }
        }
        __syncthreads();

        {
            int rw = t >> 2, gq = t & 3;
            float mold = row_m[rw];
            float mx = -CUDART_INF_F;
#pragma unroll
            for (int qq = 0; qq < 16; qq++) mx = fmaxf(mx, Ss[rw][gq * 16 + qq]);
            mx = fmaxf(mx, __shfl_xor_sync(0xffffffffu, mx, 1));
            mx = fmaxf(mx, __shfl_xor_sync(0xffffffffu, mx, 2));
            float nm = fmaxf(mold, mx);
            float alpha = (nm == -CUDART_INF_F) ? 1.f : __expf(mold - nm);
            float ps = 0.f;
#pragma unroll
            for (int qq = 0; qq < 16; qq++) {
                float sv = Ss[rw][gq * 16 + qq];
                float p = (sv == -CUDART_INF_F) ? 0.f : __expf(sv - nm);
                Ss[rw][gq * 16 + qq] = p;
                ps += p;
            }
            ps += __shfl_xor_sync(0xffffffffu, ps, 1);
            ps += __shfl_xor_sync(0xffffffffu, ps, 2);
            if (gq == 0) {
                row_m[rw] = nm;
                row_l[rw] = row_l[rw] * alpha + ps;
                row_alpha[rw] = alpha;
            }
        }
        __syncthreads();

        {
            float a0 = row_alpha[r0], a1 = row_alpha[r0 + 1];
            O0.x *= a0; O0.y *= a0; O0.z *= a0; O0.w *= a0;
            O1.x *= a1; O1.y *= a1; O1.z *= a1; O1.w *= a1;
#pragma unroll 4
            for (int j = 0; j < BN; j++) {
                float p0 = Ss[r0][j];
                float p1 = Ss[r0 + 1][j];
                const float4 v = *(const float4*)&Vs[j][dg * 4];
                O0.x = fmaf(p0, v.x, O0.x);
                O0.y = fmaf(p0, v.y, O0.y);
                O0.z = fmaf(p0, v.z, O0.z);
                O0.w = fmaf(p0, v.w, O0.w);
                O1.x = fmaf(p1, v.x, O1.x);
                O1.y = fmaf(p1, v.y, O1.y);
                O1.z = fmaf(p1, v.z, O1.z);
                O1.w = fmaf(p1, v.w, O1.w);
            }
        }
    }

    {
        size_t b0 = (((size_t)(split * NH + h)) * L + i0 + r0) * DH + dg * 4;
        *(float4*)&d_pO[b0] = O0;
        *(float4*)&d_pO[b0 + DH] = O1;
        if (t < BM) d_pml[((split * NH + h) * L) + i0 + t] = make_float2(row_m[t], row_l[t]);
    }
}

// ---------------- Kernel 5: fused combine + ds = (G*attn_out) @ Wo * mask ----------------
// A[mI][c] with c = 32h + d is built on the fly: (Σ_s cw[row][h][s] * pO[s][h][mI][d]) * G[mI][c],
// cw = exp(m_s - m_max) / Σ_s l_s exp(m_s - m_max)  (the split-softmax merge, incl. 1/l).
__global__ __launch_bounds__(256) void gemm_out_fused_kernel(const float* __restrict__ Wo,
                                                             const int* __restrict__ mask,
                                                             float* __restrict__ out) {
    __shared__ float As[64][33];
    __shared__ float Bs[32][65];
    __shared__ float cw[64][NH][NSPLIT];   // 8 KB

    int t = threadIdx.x;
    int m0 = blockIdx.x * 64, n0 = blockIdx.y * 64;
    int tx = t & 15, ty = t >> 4;

    // precompute per-(row, head) merge weights
    for (int p = t; p < 64 * NH; p += 256) {
        int row = p >> 3, h = p & 7;
        int i = m0 + row;
        float2 ml[NSPLIT];
        float mx = -CUDART_INF_F;
#pragma unroll
        for (int s = 0; s < NSPLIT; s++) {
            ml[s] = d_pml[((s * NH + h) * L) + i];
            mx = fmaxf(mx, ml[s].x);
        }
        float w[NSPLIT], lsum = 0.f;
#pragma unroll
        for (int s = 0; s < NSPLIT; s++) {
            w[s] = (ml[s].x == -CUDART_INF_F) ? 0.f : __expf(ml[s].x - mx);
            lsum = fmaf(ml[s].y, w[s], lsum);
        }
        float rl = (lsum > 0.f) ? (1.f / lsum) : 0.f;
#pragma unroll
        for (int s = 0; s < NSPLIT; s++) cw[row][h][s] = w[s] * rl;
    }
    __syncthreads();

    float acc[4][4] = {};
    int ra = t >> 2, ca = (t & 3) * 8;     // A-load mapping: row ra, 8 cols from ca
    int rb = t >> 3, cb = (t & 7) * 8;     // B-load mapping

    for (int k0 = 0; k0 < 256; k0 += 32) {
        // build A chunk via combine: h fixed per k0 (ca+q < 32)
        {
            int h = k0 >> 5;
            int iG = m0 + ra;
            float o[8] = {};
#pragma unroll
            for (int s = 0; s < NSPLIT; s++) {
                float wsc = cw[ra][h][s];
                const float* pp = &d_pO[(((size_t)(s * NH + h)) * L + iG) * DH + ca];
                float4 p0 = *(const float4*)pp;
                float4 p1 = *(const float4*)(pp + 4);
                o[0] = fmaf(wsc, p0.x, o[0]);
                o[1] = fmaf(wsc, p0.y, o[1]);
                o[2] = fmaf(wsc, p0.z, o[2]);
                o[3] = fmaf(wsc, p0.w, o[3]);
                o[4] = fmaf(wsc, p1.x, o[4]);
                o[5] = fmaf(wsc, p1.y, o[5]);
                o[6] = fmaf(wsc, p1.z, o[6]);
                o[7] = fmaf(wsc, p1.w, o[7]);
            }
            const float4 g0 = *(const float4*)&d_G[iG * CS + k0 + ca];
            const float4 g1 = *(const float4*)&d_G[iG * CS + k0 + ca + 4];
            As[ra][ca + 0] = o[0] * g0.x;
            As[ra][ca + 1] = o[1] * g0.y;
            As[ra][ca + 2] = o[2] * g0.z;
            As[ra][ca + 3] = o[3] * g0.w;
            As[ra][ca + 4] = o[4] * g1.x;
            As[ra][ca + 5] = o[5] * g1.y;
            As[ra][ca + 6] = o[6] * g1.z;
            As[ra][ca + 7] = o[7] * g1.w;
        }
#pragma unroll
        for (int q = 0; q < 8; q++) Bs[rb][cb + q] = Wo[(k0 + rb) * 256 + n0 + cb + q];
        __syncthreads();
#pragma unroll 8
        for (int kk = 0; kk < 32; kk++) {
            float a[4], bb[4];
#pragma unroll
            for (int ii = 0; ii < 4; ii++) a[ii] = As[ty * 4 + ii][kk];
#pragma unroll
            for (int jj = 0; jj < 4; jj++) bb[jj] = Bs[kk][tx * 4 + jj];
#pragma unroll
            for (int ii = 0; ii < 4; ii++)
#pragma unroll
                for (int jj = 0; jj < 4; jj++) acc[ii][jj] = fmaf(a[ii], bb[jj], acc[ii][jj]);
        }
        __syncthreads();
    }

#pragma unroll
    for (int ii = 0; ii < 4; ii++) {
        int mI = m0 + ty * 4 + ii;
        float mk = (mask[mI] != 0) ? 1.f : 0.f;
#pragma unroll
        for (int jj = 0; jj < 4; jj++) {
            int nI = n0 + tx * 4 + jj;
            out[mI * 256 + nI] = acc[ii][jj] * mk;
        }
    }
}

// ---------------- side stream (static init; deltas settle before checkpoints) ----------------
__global__ void warmup_kernel() {}

namespace {
struct SideStream {
    cudaStream_t s;
    cudaEvent_t fork, join;
    SideStream() {
        cudaStreamCreateWithFlags(&s, cudaStreamNonBlocking);
        cudaEventCreateWithFlags(&fork, cudaEventDisableTiming);
        cudaEventCreateWithFlags(&join, cudaEventDisableTiming);
        warmup_kernel<<<1, 32, 0, s>>>();
        warmup_kernel<<<1, 32>>>();
        cudaDeviceSynchronize();
    }
};
SideStream g_ss;
}

// ---------------- launch (R11 schedule; combine fused into output GEMM) ----------------
extern "C" void kernel_launch(void* const* d_in, const int* in_sizes, int n_in,
                              void* d_out, int out_size) {
    const float* s = (const float*)d_in[0];
    const float* z = (const float*)d_in[1];
    const int* res_mask = (const int*)d_in[2];
    const float* g_s = (const float*)d_in[3];
    const float* b_s = (const float*)d_in[4];
    const float* g_z = (const float*)d_in[5];
    const float* b_z = (const float*)d_in[6];
    const float* Wq = (const float*)d_in[7];
    const float* bq = (const float*)d_in[8];
    const float* Wk = (const float*)d_in[9];
    const float* Wv = (const float*)d_in[10];
    const float* Wb = (const float*)d_in[11];
    const float* Wg = (const float*)d_in[12];
    const float* Wo = (const float*)d_in[13];
    float* out = (float*)d_out;

    cudaEventRecord(g_ss.fork, 0);
    cudaStreamWaitEvent(g_ss.s, g_ss.fork, 0);

    zprep_kernel<<<1, 256, 0, g_ss.s>>>(g_z, b_z, Wb);
    zln_bias_kernel<<<dim3(16, L), 256, 0, g_ss.s>>>(z);

    ln_s_kernel<<<L, 256>>>(s, g_s, b_s);
    gemm_qkvg_kernel<<<dim3(16, 4, 4), 256>>>(Wq, bq, Wk, Wv, Wg);

    cudaEventRecord(g_ss.join, g_ss.s);
    cudaStreamWaitEvent(0, g_ss.join, 0);

    attn_split_kernel<<<dim3(16, 8, NSPLIT), 256>>>(res_mask);
    gemm_out_fused_kernel<<<dim3(16, 4), 256>>>(Wo, res_mask, out);
}

// round 16
// speedup vs baseline: 1.1052x; 1.0271x over previous
#include <cuda_runtime.h>
#include <math_constants.h>

#define L 1024
#define CS 256
#define CZ 128
#define NH 8
#define DH 32
#define NSPLIT 4
#define BM 64
#define BN 64
#define LN_EPS 1e-5f
#define QK_SCALE 0.17677669529663687f  // 1/sqrt(32)

// f32x2 packed math (sm_103a)
#define PACKF2(d, lo, hi) \
    asm("mov.b64 %0, {%1, %2};" : "=l"(d) : "r"(__float_as_uint(lo)), "r"(__float_as_uint(hi)))
#define UNPACKF2(lo, hi, v) \
    do { unsigned _ulo, _uhi; \
         asm("mov.b64 {%0, %1}, %2;" : "=r"(_ulo), "=r"(_uhi) : "l"(v)); \
         lo = __uint_as_float(_ulo); hi = __uint_as_float(_uhi); } while (0)
#define FMA_F32X2(d, a, b, c) \
    asm("fma.rn.f32x2 %0, %1, %2, %3;" : "=l"(d) : "l"(a), "l"(b), "l"(c))
#define ADD_F32X2(d, a, b) \
    asm("add.rn.f32x2 %0, %1, %2;" : "=l"(d) : "l"(a), "l"(b))

// 16B-group swizzled slot for d-tiles: row r (0..63), 16B group d4 (0..7)
#define KSLOT(r, d4) ((r) * 32 + (((d4) ^ (((r) >> 2) & 7)) << 2))

// ---------------- scratch (device globals; no allocation allowed) ----------------
__device__ float d_sln[L * CS];
__device__ float d_Q[L * CS];
__device__ float d_K[L * CS];
__device__ float d_V[L * CS];
__device__ float d_G[L * CS];
__device__ float d_Bt[(size_t)L * NH * L];             // bias transposed: [i][h][j], 32 MB
__device__ float d_AO[L * CS];                         // G * attn_out
__device__ float d_pO[NSPLIT * NH * L * DH];           // split attention partial O
__device__ float2 d_pml[NSPLIT * NH * L];              // split attention partial (m, l)
__device__ float4 d_GW4g[256];                         // packed g*Wb, idx q*32+h*4+k, c=(q+8k)*4
__device__ float d_SgWg[NH], d_SbWg[NH];

// ---------------- Kernel 0: one-block prep of GW / SgW / SbW ----------------
__global__ __launch_bounds__(256) void zprep_kernel(const float* __restrict__ gz,
                                                    const float* __restrict__ bz,
                                                    const float* __restrict__ Wb) {
    int t = threadIdx.x;
    {
        int q = t >> 5, h = (t >> 2) & 7, k = t & 3;
        int c = (q + 8 * k) * 4;
        d_GW4g[q * 32 + h * 4 + k] =
            make_float4(gz[c] * Wb[c * NH + h], gz[c + 1] * Wb[(c + 1) * NH + h],
                        gz[c + 2] * Wb[(c + 2) * NH + h], gz[c + 3] * Wb[(c + 3) * NH + h]);
    }
    if (t < 16) {
        int h = t & 7;
        float acc = 0.f;
        if (t < 8) {
            for (int c = 0; c < CZ; c++) acc = fmaf(gz[c], Wb[c * NH + h], acc);
            d_SgWg[h] = acc;
        } else {
            for (int c = 0; c < CZ; c++) acc = fmaf(bz[c], Wb[c * NH + h], acc);
            d_SbWg[h] = acc;
        }
    }
}

// ---------------- Kernel 1: LayerNorm(s) ----------------
__global__ __launch_bounds__(256) void ln_s_kernel(const float* __restrict__ s,
                                                   const float* __restrict__ g,
                                                   const float* __restrict__ b) {
    int r = blockIdx.x, t = threadIdx.x;
    float v = s[r * CS + t];
    __shared__ float red[8];

    float sum = v;
#pragma unroll
    for (int off = 16; off > 0; off >>= 1) sum += __shfl_xor_sync(0xffffffffu, sum, off);
    if ((t & 31) == 0) red[t >> 5] = sum;
    __syncthreads();
    float tot = 0.f;
#pragma unroll
    for (int k = 0; k < 8; k++) tot += red[k];
    float mean = tot * (1.f / CS);
    float d = v - mean;
    __syncthreads();

    float sq = d * d;
#pragma unroll
    for (int off = 16; off > 0; off >>= 1) sq += __shfl_xor_sync(0xffffffffu, sq, off);
    if ((t & 31) == 0) red[t >> 5] = sq;
    __syncthreads();
    float tot2 = 0.f;
#pragma unroll
    for (int k = 0; k < 8; k++) tot2 += red[k];
    float rstd = rsqrtf(tot2 * (1.f / CS) + LN_EPS);

    d_sln[r * CS + t] = d * rstd * g[t] + b[t];
}

// ---------------- shared GEMM tile helper ----------------
__device__ __forceinline__ void gemm_tile_64x64(const float* __restrict__ A,
                                                const float* __restrict__ Bm,
                                                int m0, int n0, float acc[4][4]) {
    __shared__ float As[64][33];
    __shared__ float Bs[32][65];
    int t = threadIdx.x;
    int tx = t & 15, ty = t >> 4;

    for (int k0 = 0; k0 < 256; k0 += 32) {
        int ra = t >> 2, ca = (t & 3) * 8;
#pragma unroll
        for (int q = 0; q < 8; q++) As[ra][ca + q] = A[(m0 + ra) * 256 + k0 + ca + q];
        int rb = t >> 3, cb = (t & 7) * 8;
#pragma unroll
        for (int q = 0; q < 8; q++) Bs[rb][cb + q] = Bm[(k0 + rb) * 256 + n0 + cb + q];
        __syncthreads();
#pragma unroll 8
        for (int kk = 0; kk < 32; kk++) {
            float a[4], bb[4];
#pragma unroll
            for (int ii = 0; ii < 4; ii++) a[ii] = As[ty * 4 + ii][kk];
#pragma unroll
            for (int jj = 0; jj < 4; jj++) bb[jj] = Bs[kk][tx * 4 + jj];
#pragma unroll
            for (int ii = 0; ii < 4; ii++)
#pragma unroll
                for (int jj = 0; jj < 4; jj++) acc[ii][jj] = fmaf(a[ii], bb[jj], acc[ii][jj]);
        }
        __syncthreads();
    }
}

// ---------------- Kernel 2: QKVG projections ----------------
__global__ __launch_bounds__(256) void gemm_qkvg_kernel(const float* __restrict__ Wq,
                                                        const float* __restrict__ bq,
                                                        const float* __restrict__ Wk,
                                                        const float* __restrict__ Wv,
                                                        const float* __restrict__ Wg) {
    const float* Bm;
    float* C;
    int mode;
    switch (blockIdx.z) {
        case 0: Bm = Wq; C = d_Q; mode = 1; break;
        case 1: Bm = Wk; C = d_K; mode = 0; break;
        case 2: Bm = Wv; C = d_V; mode = 0; break;
        default: Bm = Wg; C = d_G; mode = 2; break;
    }
    int m0 = blockIdx.x * 64, n0 = blockIdx.y * 64;
    float acc[4][4] = {};
    gemm_tile_64x64(d_sln, Bm, m0, n0, acc);

    int tx = threadIdx.x & 15, ty = threadIdx.x >> 4;
#pragma unroll
    for (int ii = 0; ii < 4; ii++)
#pragma unroll
        for (int jj = 0; jj < 4; jj++) {
            int mI = m0 + ty * 4 + ii, nI = n0 + tx * 4 + jj;
            float v = acc[ii][jj];
            if (mode == 1) v += bq[nI];
            if (mode == 2) v = 1.f / (1.f + __expf(-v));
            C[mI * 256 + nI] = v;
        }
}

// ---------------- Kernel 3: zln_bias v9 (R13 exact — proven 123.8us) ----------------
__global__ __launch_bounds__(256, 3) void zln_bias_kernel(const float* __restrict__ z) {
    __shared__ ulonglong2 GW2[8][33];
    __shared__ float sB[NH * 68];

    int t = threadIdx.x;
    int i = blockIdx.y;
    int jbase = blockIdx.x * 64;
    int rr = t >> 3, q = t & 7;

    {
        float4 w = d_GW4g[t];
        ulonglong2 p;
        PACKF2(p.x, w.x, w.y);
        PACKF2(p.y, w.z, w.w);
        GW2[t >> 5][t & 31] = p;
    }
    float Sg = d_SgWg[q], Sb = d_SbWg[q];
    __syncthreads();

    const float* rowA = z + ((size_t)i * L + jbase + rr) * CZ;
    const float* rowB = rowA + (size_t)32 * CZ;

    unsigned long long paA[8] = {}, paB[8] = {};
    unsigned long long s1A = 0ull, s2A = 0ull, s1B = 0ull, s2B = 0ull;
#pragma unroll
    for (int k = 0; k < 4; k++) {
        int off = (q + 8 * k) * 4;
        const float4 va = *(const float4*)(rowA + off);
        const float4 vb = *(const float4*)(rowB + off);
        unsigned long long a01, a23, b01, b23;
        PACKF2(a01, va.x, va.y);
        PACKF2(a23, va.z, va.w);
        PACKF2(b01, vb.x, vb.y);
        PACKF2(b23, vb.z, vb.w);
#pragma unroll
        for (int h = 0; h < 8; h++) {
            ulonglong2 w = GW2[q][h * 4 + k];
            FMA_F32X2(paA[h], a01, w.x, paA[h]);
            FMA_F32X2(paA[h], a23, w.y, paA[h]);
            FMA_F32X2(paB[h], b01, w.x, paB[h]);
            FMA_F32X2(paB[h], b23, w.y, paB[h]);
        }
        FMA_F32X2(s2A, a01, a01, s2A);
        FMA_F32X2(s2A, a23, a23, s2A);
        ADD_F32X2(s1A, s1A, a01);
        ADD_F32X2(s1A, s1A, a23);
        FMA_F32X2(s2B, b01, b01, s2B);
        FMA_F32X2(s2B, b23, b23, s2B);
        ADD_F32X2(s1B, s1B, b01);
        ADD_F32X2(s1B, s1B, b23);
    }

    float vA[8], vB[8];
#pragma unroll
    for (int h = 0; h < 8; h++) {
        float lo, hi;
        UNPACKF2(lo, hi, paA[h]);
        vA[h] = lo + hi;
        UNPACKF2(lo, hi, paB[h]);
        vB[h] = lo + hi;
    }
    float s1Af, s2Af, s1Bf, s2Bf;
    {
        float l1, h1;
        UNPACKF2(l1, h1, s1A); s1Af = l1 + h1;
        UNPACKF2(l1, h1, s2A); s2Af = l1 + h1;
        UNPACKF2(l1, h1, s1B); s1Bf = l1 + h1;
        UNPACKF2(l1, h1, s2B); s2Bf = l1 + h1;
    }

    bool h4 = (t & 4) != 0;
    float wA[4], wB[4];
#pragma unroll
    for (int k = 0; k < 4; k++) {
        float sA = h4 ? vA[k] : vA[k + 4];
        float sBv = h4 ? vB[k] : vB[k + 4];
        float rA = __shfl_xor_sync(0xffffffffu, sA, 4);
        float rB = __shfl_xor_sync(0xffffffffu, sBv, 4);
        wA[k] = (h4 ? vA[k + 4] : vA[k]) + rA;
        wB[k] = (h4 ? vB[k + 4] : vB[k]) + rB;
    }
    bool h2 = (t & 2) != 0;
    float xA[2], xB[2];
#pragma unroll
    for (int k = 0; k < 2; k++) {
        float sA = h2 ? wA[k] : wA[k + 2];
        float sBv = h2 ? wB[k] : wB[k + 2];
        float rA = __shfl_xor_sync(0xffffffffu, sA, 2);
        float rB = __shfl_xor_sync(0xffffffffu, sBv, 2);
        xA[k] = (h2 ? wA[k + 2] : wA[k]) + rA;
        xB[k] = (h2 ? wB[k + 2] : wB[k]) + rB;
    }
    bool h1 = (t & 1) != 0;
    float aA, aB;
    {
        float sA = h1 ? xA[0] : xA[1];
        float sBv = h1 ? xB[0] : xB[1];
        float rA = __shfl_xor_sync(0xffffffffu, sA, 1);
        float rB = __shfl_xor_sync(0xffffffffu, sBv, 1);
        aA = (h1 ? xA[1] : xA[0]) + rA;
        aB = (h1 ? xB[1] : xB[0]) + rB;
    }
#pragma unroll
    for (int m = 4; m > 0; m >>= 1) {
        s1Af += __shfl_xor_sync(0xffffffffu, s1Af, m);
        s2Af += __shfl_xor_sync(0xffffffffu, s2Af, m);
        s1Bf += __shfl_xor_sync(0xffffffffu, s1Bf, m);
        s2Bf += __shfl_xor_sync(0xffffffffu, s2Bf, m);
    }

    {
        float meanA = s1Af * (1.f / CZ);
        float rstdA = rsqrtf(s2Af * (1.f / CZ) - meanA * meanA + LN_EPS);
        float mrA = meanA * rstdA;
        sB[q * 68 + rr] = rstdA * aA - mrA * Sg + Sb;

        float meanB = s1Bf * (1.f / CZ);
        float rstdB = rsqrtf(s2Bf * (1.f / CZ) - meanB * meanB + LN_EPS);
        float mrB = meanB * rstdB;
        sB[q * 68 + rr + 32] = rstdB * aB - mrB * Sg + Sb;
    }
    __syncthreads();

    {
        int h = t >> 5, col = t & 31;
        size_t base = ((size_t)i * NH + h) * L + jbase;
        d_Bt[base + col] = sB[h * 68 + col];
        d_Bt[base + col + 32] = sB[h * 68 + col + 32];
    }
}

// ---------------- Kernel 4a: split attention — vectorized softmax + PV (Ss stride 68) ----------------
__global__ __launch_bounds__(256, 3) void attn_split_kernel(const int* __restrict__ mask) {
    __shared__ float Qs[BM * 32];        // swizzled KSLOT layout
    __shared__ float Ks[BN * 32];        // swizzled
    __shared__ float Vs[BN][32];
    __shared__ float Ss[BM][68];         // 16B-aligned rows (272 B stride)
    __shared__ float row_m[BM], row_l[BM], row_alpha[BM];
    __shared__ unsigned char ms[BN];

    int t = threadIdx.x;
    int h = blockIdx.y;
    int i0 = blockIdx.x * BM;
    int split = blockIdx.z;
    int tx = t & 15, ty = t >> 4;

#pragma unroll
    for (int rep = 0; rep < 2; rep++) {
        int idx = t + rep * 256;
        int r = idx >> 3, c4 = idx & 7;
        float4 q4 = *(const float4*)&d_Q[(i0 + r) * CS + h * DH + c4 * 4];
        q4.x *= QK_SCALE; q4.y *= QK_SCALE; q4.z *= QK_SCALE; q4.w *= QK_SCALE;
        *(float4*)&Qs[KSLOT(r, c4)] = q4;
    }
    if (t < BM) { row_m[t] = -CUDART_INF_F; row_l[t] = 0.f; }

    int dg = t & 7;
    int r0 = (t >> 3) * 2;
    float4 O0 = make_float4(0.f, 0.f, 0.f, 0.f);
    float4 O1 = make_float4(0.f, 0.f, 0.f, 0.f);

    for (int jt = 0; jt < 4; jt++) {
        int j0 = split * 256 + jt * BN;
        __syncthreads();
#pragma unroll
        for (int rep = 0; rep < 2; rep++) {
            int idx = t + rep * 256;
            int r = idx >> 3, c4 = idx & 7;
            float4 k4 = *(const float4*)&d_K[(j0 + r) * CS + h * DH + c4 * 4];
            *(float4*)&Ks[KSLOT(r, c4)] = k4;
            *(float4*)&Vs[r][c4 * 4] = *(const float4*)&d_V[(j0 + r) * CS + h * DH + c4 * 4];
        }
        if (t < BN) ms[t] = (unsigned char)(mask[j0 + t] != 0);
        __syncthreads();

        // S = Q K^T via LDS.128
        float sacc[4][4] = {};
#pragma unroll
        for (int d4 = 0; d4 < 8; d4++) {
            float4 a4[4];
#pragma unroll
            for (int ii = 0; ii < 4; ii++) a4[ii] = *(const float4*)&Qs[KSLOT(ty * 4 + ii, d4)];
#pragma unroll
            for (int jj = 0; jj < 4; jj++) {
                float4 b4 = *(const float4*)&Ks[KSLOT(tx * 4 + jj, d4)];
#pragma unroll
                for (int ii = 0; ii < 4; ii++) {
                    sacc[ii][jj] = fmaf(a4[ii].x, b4.x, sacc[ii][jj]);
                    sacc[ii][jj] = fmaf(a4[ii].y, b4.y, sacc[ii][jj]);
                    sacc[ii][jj] = fmaf(a4[ii].z, b4.z, sacc[ii][jj]);
                    sacc[ii][jj] = fmaf(a4[ii].w, b4.w, sacc[ii][jj]);
                }
            }
        }
#pragma unroll
        for (int ii = 0; ii < 4; ii++) {
            int iI = ty * 4 + ii;
            const float4 bv = *(const float4*)&d_Bt[(size_t)(i0 + iI) * (NH * L) + h * L + j0 + tx * 4];
            float bb4[4] = {bv.x, bv.y, bv.z, bv.w};
#pragma unroll
            for (int jj = 0; jj < 4; jj++) {
                int jl = tx * 4 + jj;
                Ss[iI][jl] = ms[jl] ? (sacc[ii][jj] + bb4[jj]) : -CUDART_INF_F;
            }
        }
        __syncthreads();

        // vectorized online softmax: rw = t>>2 (64 rows), gq = t&3 (16 j each via 4 float4)
        {
            int rw = t >> 2, gq = t & 3;
            float mold = row_m[rw];
            float4 sv4[4];
#pragma unroll
            for (int g = 0; g < 4; g++) sv4[g] = *(const float4*)&Ss[rw][gq * 16 + g * 4];
            float mx = -CUDART_INF_F;
#pragma unroll
            for (int g = 0; g < 4; g++) {
                mx = fmaxf(mx, fmaxf(fmaxf(sv4[g].x, sv4[g].y), fmaxf(sv4[g].z, sv4[g].w)));
            }
            mx = fmaxf(mx, __shfl_xor_sync(0xffffffffu, mx, 1));
            mx = fmaxf(mx, __shfl_xor_sync(0xffffffffu, mx, 2));
            float nm = fmaxf(mold, mx);
            float alpha = (nm == -CUDART_INF_F) ? 1.f : __expf(mold - nm);
            float ps = 0.f;
#pragma unroll
            for (int g = 0; g < 4; g++) {
                float4 p;
                p.x = (sv4[g].x == -CUDART_INF_F) ? 0.f : __expf(sv4[g].x - nm);
                p.y = (sv4[g].y == -CUDART_INF_F) ? 0.f : __expf(sv4[g].y - nm);
                p.z = (sv4[g].z == -CUDART_INF_F) ? 0.f : __expf(sv4[g].z - nm);
                p.w = (sv4[g].w == -CUDART_INF_F) ? 0.f : __expf(sv4[g].w - nm);
                *(float4*)&Ss[rw][gq * 16 + g * 4] = p;
                ps += p.x + p.y + p.z + p.w;
            }
            ps += __shfl_xor_sync(0xffffffffu, ps, 1);
            ps += __shfl_xor_sync(0xffffffffu, ps, 2);
            if (gq == 0) {
                row_m[rw] = nm;
                row_l[rw] = row_l[rw] * alpha + ps;
                row_alpha[rw] = alpha;
            }
        }
        __syncthreads();

        // vectorized PV: 4 j per step, 6 LDS.128 per 32 FMA
        {
            float a0 = row_alpha[r0], a1 = row_alpha[r0 + 1];
            O0.x *= a0; O0.y *= a0; O0.z *= a0; O0.w *= a0;
            O1.x *= a1; O1.y *= a1; O1.z *= a1; O1.w *= a1;
#pragma unroll 4
            for (int jg = 0; jg < 16; jg++) {
                const float4 p0 = *(const float4*)&Ss[r0][jg * 4];
                const float4 p1 = *(const float4*)&Ss[r0 + 1][jg * 4];
                const float4 v0 = *(const float4*)&Vs[jg * 4 + 0][dg * 4];
                const float4 v1 = *(const float4*)&Vs[jg * 4 + 1][dg * 4];
                const float4 v2 = *(const float4*)&Vs[jg * 4 + 2][dg * 4];
                const float4 v3 = *(const float4*)&Vs[jg * 4 + 3][dg * 4];
                O0.x = fmaf(p0.x, v0.x, O0.x); O0.y = fmaf(p0.x, v0.y, O0.y);
                O0.z = fmaf(p0.x, v0.z, O0.z); O0.w = fmaf(p0.x, v0.w, O0.w);
                O0.x = fmaf(p0.y, v1.x, O0.x); O0.y = fmaf(p0.y, v1.y, O0.y);
                O0.z = fmaf(p0.y, v1.z, O0.z); O0.w = fmaf(p0.y, v1.w, O0.w);
                O0.x = fmaf(p0.z, v2.x, O0.x); O0.y = fmaf(p0.z, v2.y, O0.y);
                O0.z = fmaf(p0.z, v2.z, O0.z); O0.w = fmaf(p0.z, v2.w, O0.w);
                O0.x = fmaf(p0.w, v3.x, O0.x); O0.y = fmaf(p0.w, v3.y, O0.y);
                O0.z = fmaf(p0.w, v3.z, O0.z); O0.w = fmaf(p0.w, v3.w, O0.w);
                O1.x = fmaf(p1.x, v0.x, O1.x); O1.y = fmaf(p1.x, v0.y, O1.y);
                O1.z = fmaf(p1.x, v0.z, O1.z); O1.w = fmaf(p1.x, v0.w, O1.w);
                O1.x = fmaf(p1.y, v1.x, O1.x); O1.y = fmaf(p1.y, v1.y, O1.y);
                O1.z = fmaf(p1.y, v1.z, O1.z); O1.w = fmaf(p1.y, v1.w, O1.w);
                O1.x = fmaf(p1.z, v2.x, O1.x); O1.y = fmaf(p1.z, v2.y, O1.y);
                O1.z = fmaf(p1.z, v2.z, O1.z); O1.w = fmaf(p1.z, v2.w, O1.w);
                O1.x = fmaf(p1.w, v3.x, O1.x); O1.y = fmaf(p1.w, v3.y, O1.y);
                O1.z = fmaf(p1.w, v3.z, O1.z); O1.w = fmaf(p1.w, v3.w, O1.w);
            }
        }
    }

    {
        size_t b0 = (((size_t)(split * NH + h)) * L + i0 + r0) * DH + dg * 4;
        *(float4*)&d_pO[b0] = O0;
        *(float4*)&d_pO[b0 + DH] = O1;
        if (t < BM) d_pml[((split * NH + h) * L) + i0 + t] = make_float2(row_m[t], row_l[t]);
    }
}

// ---------------- Kernel 4b: combine splits, apply 1/l and G gate ----------------
__global__ __launch_bounds__(256) void attn_combine_kernel() {
    int t = threadIdx.x;
    int i = blockIdx.x;
    int h = t >> 5, lane = t & 31;

    float2 ml[NSPLIT];
    float mx = -CUDART_INF_F;
#pragma unroll
    for (int s = 0; s < NSPLIT; s++) {
        ml[s] = d_pml[((s * NH + h) * L) + i];
        mx = fmaxf(mx, ml[s].x);
    }
    float lsum = 0.f, o = 0.f;
#pragma unroll
    for (int s = 0; s < NSPLIT; s++) {
        float w = (ml[s].x == -CUDART_INF_F) ? 0.f : __expf(ml[s].x - mx);
        lsum = fmaf(ml[s].y, w, lsum);
        o = fmaf(d_pO[(((s * NH + h) * L) + i) * DH + lane], w, o);
    }
    float rl = (lsum > 0.f) ? (1.f / lsum) : 0.f;
    int base = i * CS + h * DH + lane;
    d_AO[base] = o * rl * d_G[base];
}

// ---------------- Kernel 5: ds = (G*out) @ Wo * mask ----------------
__global__ __launch_bounds__(256) void gemm_out_kernel(const float* __restrict__ Wo,
                                                       const int* __restrict__ mask,
                                                       float* __restrict__ out) {
    int m0 = blockIdx.x * 64, n0 = blockIdx.y * 64;
    float acc[4][4] = {};
    gemm_tile_64x64(d_AO, Wo, m0, n0, acc);

    int tx = threadIdx.x & 15, ty = threadIdx.x >> 4;
#pragma unroll
    for (int ii = 0; ii < 4; ii++) {
        int mI = m0 + ty * 4 + ii;
        float mk = (mask[mI] != 0) ? 1.f : 0.f;
#pragma unroll
        for (int jj = 0; jj < 4; jj++) {
            int nI = n0 + tx * 4 + jj;
            out[mI * 256 + nI] = acc[ii][jj] * mk;
        }
    }
}

// ---------------- side stream (static init; deltas settle before checkpoints) ----------------
__global__ void warmup_kernel() {}

namespace {
struct SideStream {
    cudaStream_t s;
    cudaEvent_t fork, join;
    SideStream() {
        cudaStreamCreateWithFlags(&s, cudaStreamNonBlocking);
        cudaEventCreateWithFlags(&fork, cudaEventDisableTiming);
        cudaEventCreateWithFlags(&join, cudaEventDisableTiming);
        warmup_kernel<<<1, 32, 0, s>>>();
        warmup_kernel<<<1, 32>>>();
        cudaDeviceSynchronize();
    }
};
SideStream g_ss;
}

// ---------------- launch (R11/R13 schedule) ----------------
extern "C" void kernel_launch(void* const* d_in, const int* in_sizes, int n_in,
                              void* d_out, int out_size) {
    const float* s = (const float*)d_in[0];
    const float* z = (const float*)d_in[1];
    const int* res_mask = (const int*)d_in[2];
    const float* g_s = (const float*)d_in[3];
    const float* b_s = (const float*)d_in[4];
    const float* g_z = (const float*)d_in[5];
    const float* b_z = (const float*)d_in[6];
    const float* Wq = (const float*)d_in[7];
    const float* bq = (const float*)d_in[8];
    const float* Wk = (const float*)d_in[9];
    const float* Wv = (const float*)d_in[10];
    const float* Wb = (const float*)d_in[11];
    const float* Wg = (const float*)d_in[12];
    const float* Wo = (const float*)d_in[13];
    float* out = (float*)d_out;

    cudaEventRecord(g_ss.fork, 0);
    cudaStreamWaitEvent(g_ss.s, g_ss.fork, 0);

    zprep_kernel<<<1, 256, 0, g_ss.s>>>(g_z, b_z, Wb);
    zln_bias_kernel<<<dim3(16, L), 256, 0, g_ss.s>>>(z);

    ln_s_kernel<<<L, 256>>>(s, g_s, b_s);
    gemm_qkvg_kernel<<<dim3(16, 4, 4), 256>>>(Wq, bq, Wk, Wv, Wg);

    cudaEventRecord(g_ss.join, g_ss.s);
    cudaStreamWaitEvent(0, g_ss.join, 0);

    attn_split_kernel<<<dim3(16, 8, NSPLIT), 256>>>(res_mask);
    attn_combine_kernel<<<L, 256>>>();
    gemm_out_kernel<<<dim3(16, 4), 256>>>(Wo, res_mask, out);
}